// round 15
// baseline (speedup 1.0000x reference)
#include <cuda_runtime.h>
#include <cuda_fp16.h>
#include <cstdint>

// ----------------------------------------------------------------------------
// Decoder_61237643706389 — mma.sync HMMA fp16 2-product path, round 15.
// Change vs r14 (681us): 4-warp blocks (128 threads, 2m x 2n), warp tile
// 48ch x 32u -> the 6 A-fragment LDG.128 per warp-kstep now feed 24 mma
// (was 12), halving the A L1 stream (the measured 75% binder).
// ----------------------------------------------------------------------------

typedef unsigned int       u32;
typedef unsigned long long u64;

#define G        32
#define NBATCH   2
#define CCH      96
#define NPTS     32768
#define OUTC     45
#define NP       8
#define NU       64
#define THREADS  128

#define S_H      92             // H row stride in 32-bit words (92 mod 32 = 28)
#define YSTR     65             // yf row stride in floats

// dynamic smem layout (bytes)
#define SM_H     0                          // H fp16: 64 rows x 92 words = 23552
#define SM_YF    23552                      // yf fp32 [96][YSTR] = 24960
#define SM_TOT   (23552 + CCH * YSTR * 4)   // 48512

// Transposed context features: [B][x][y][z][C], contiguous C.
__device__ float g_cvt[NBATCH * NPTS * CCH];
// Pre-packed A fragments (fp16): idx = ((sg*6 + mtg)*2 + split)*32 + lane.
#define NSG 46
__device__ uint4 g_wf[NSG * 12 * 32];

__device__ __forceinline__ float silu_f(float x) {
    return x / (1.0f + __expf(-x));
}
__device__ __forceinline__ unsigned short hbits(float v) {
    __half h = __float2half(v);
    return *reinterpret_cast<unsigned short*>(&h);
}
__device__ __forceinline__ float hval(float v) {
    return __half2float(__float2half(v));
}

__device__ __forceinline__ void mma16816(float (&d)[4], uint4 a, u32 b0, u32 b1) {
    asm volatile(
        "mma.sync.aligned.m16n8k16.row.col.f32.f16.f16.f32 "
        "{%0,%1,%2,%3}, {%4,%5,%6,%7}, {%8,%9}, {%0,%1,%2,%3};"
        : "+f"(d[0]), "+f"(d[1]), "+f"(d[2]), "+f"(d[3])
        : "r"(a.x), "r"(a.y), "r"(a.z), "r"(a.w), "r"(b0), "r"(b1));
}

// write one activation value (fp16) into H. u = unit, k = row.
__device__ __forceinline__ void write_h(char* sm, int u, int k, float v) {
    int off = (u * S_H + (k >> 1)) * 4 + (k & 1) * 2;
    *reinterpret_cast<unsigned short*>(sm + SM_H + off) = hbits(v);
}

// ---------------------------------------------------------------------------
// Merged prep: blocks [0,1024) transpose context_v; blocks [1024,..) pack
// weights into mma A-fragment layout (fp16 hi/lo split).
// ---------------------------------------------------------------------------
__global__ void prep_kernel(const float* __restrict__ ctx,
                            const float* __restrict__ w00, const float* __restrict__ w01,
                            const float* __restrict__ w02, const float* __restrict__ w10,
                            const float* __restrict__ w11, const float* __restrict__ w12) {
    __shared__ float tile[CCH][65];
    if (blockIdx.x < 1024) {
        int bs = blockIdx.x;
        int b  = bs >> 9;
        int s0 = (bs & 511) * 64;
        for (int idx = threadIdx.x; idx < CCH * 64; idx += blockDim.x) {
            int c = idx >> 6, so = idx & 63;
            tile[c][so] = ctx[((long)(b * CCH + c) << 15) + s0 + so];
        }
        __syncthreads();
        for (int idx = threadIdx.x; idx < CCH * 64; idx += blockDim.x) {
            int so = idx / CCH, c = idx % CCH;
            g_cvt[(((long)b << 15) + s0 + so) * CCH + c] = tile[c][so];
        }
        return;
    }
    int idx = (blockIdx.x - 1024) * blockDim.x + threadIdx.x;
    if (idx >= NSG * 12 * 32) return;
    int lane = idx & 31;
    int t = idx >> 5;
    int split = t & 1; t >>= 1;
    int mtg = t % 6;
    int sg = t / 6;
    const float* W; int K; int sb;
    if      (sg < 11) { W = w00; K = 174; sb = 0;  }
    else if (sg < 17) { W = w01; K = 96;  sb = 11; }
    else if (sg < 23) { W = w02; K = 96;  sb = 17; }
    else if (sg < 34) { W = w10; K = 174; sb = 23; }
    else if (sg < 40) { W = w11; K = 96;  sb = 34; }
    else              { W = w12; K = 96;  sb = 40; }
    int k0 = (sg - sb) * 16 + 2 * (lane & 3);
    int m0 = mtg * 16 + (lane >> 2);

    auto get = [&](int k, int m) -> u32 {
        float v = (k < K) ? __ldg(W + k * 96 + m) : 0.0f;
        float h = hval(v);
        return (u32)hbits(split ? (v - h) : v);
    };
    uint4 r;
    r.x = get(k0, m0)     | (get(k0 + 1, m0)     << 16);
    r.y = get(k0, m0 + 8) | (get(k0 + 1, m0 + 8) << 16);
    r.z = get(k0 + 8, m0)     | (get(k0 + 9, m0)     << 16);
    r.w = get(k0 + 8, m0 + 8) | (get(k0 + 9, m0 + 8) << 16);
    g_wf[idx] = r;
}

// ---------------------------------------------------------------------------
// One MLP layer on tensor cores. Warp (wm, wn): 48ch x 32u -> 3mt x 4nt tiles,
// 2 products (Whi*H + Wlo*H) per tile per k-step.
// ---------------------------------------------------------------------------
template <int K16, int BASE, bool RES, bool WRITEH>
__device__ __forceinline__ void run_layer(char* sm, const float* __restrict__ bias,
                                          int lane, int wm, int wn) {
    float* yf = reinterpret_cast<float*>(sm + SM_YF);
    const u32* Hp = reinterpret_cast<const u32*>(sm + SM_H);

    float d[3][4][4];
#pragma unroll
    for (int mt = 0; mt < 3; ++mt) {
        int r0 = wm * 48 + mt * 16 + (lane >> 2);
        float blo = __ldg(bias + r0), bhi = __ldg(bias + r0 + 8);
#pragma unroll
        for (int nt = 0; nt < 4; ++nt) {
            d[mt][nt][0] = blo; d[mt][nt][1] = blo;
            d[mt][nt][2] = bhi; d[mt][nt][3] = bhi;
        }
    }

    const uint4* ap = g_wf + (size_t)((BASE * 6 + wm * 3) * 2) * 32 + lane;
    const int wbase = (wn * 32 + (lane >> 2)) * S_H + (lane & 3);

#pragma unroll 2
    for (int s = 0; s < K16; ++s) {
        u32 bh[4][2];
#pragma unroll
        for (int nt = 0; nt < 4; ++nt) {
            int w = wbase + nt * 8 * S_H + s * 8;
            bh[nt][0] = Hp[w]; bh[nt][1] = Hp[w + 4];
        }
        const uint4* aps = ap + (size_t)s * 384;
#pragma unroll
        for (int mt = 0; mt < 3; ++mt) {
            uint4 ah = __ldg(aps + mt * 64);
            uint4 al = __ldg(aps + mt * 64 + 32);
#pragma unroll
            for (int nt = 0; nt < 4; ++nt) {
                mma16816(d[mt][nt], ah, bh[nt][0], bh[nt][1]);
                mma16816(d[mt][nt], al, bh[nt][0], bh[nt][1]);
            }
        }
    }
    __syncthreads();   // all warps done reading H before overwriting

#pragma unroll
    for (int mt = 0; mt < 3; ++mt) {
        int r0 = wm * 48 + mt * 16 + (lane >> 2);
#pragma unroll
        for (int nt = 0; nt < 4; ++nt) {
            int c0 = wn * 32 + nt * 8 + 2 * (lane & 3);
            int rr[4] = { r0, r0, r0 + 8, r0 + 8 };
            int cc[4] = { c0, c0 + 1, c0, c0 + 1 };
#pragma unroll
            for (int e = 0; e < 4; ++e) {
                float h = silu_f(d[mt][nt][e]);
                if (RES) {
                    h += yf[rr[e] * YSTR + cc[e]];
                    yf[rr[e] * YSTR + cc[e]] = h;
                }
                if (WRITEH) write_h(sm, cc[e], rr[e], h);
            }
        }
    }
    __syncthreads();
}

// ---------------------------------------------------------------------------
// Main kernel: 8 points x 8 corners = 64 units, 128 threads (4 warps).
// ---------------------------------------------------------------------------
__global__ void __launch_bounds__(THREADS, 4)
decoder_kernel(const float* __restrict__ qw_g,
               const int* __restrict__ mask_g,
               const float* __restrict__ grid_g,
               const float* __restrict__ affine_g,
               const float* __restrict__ b00, const float* __restrict__ b01,
               const float* __restrict__ b02, const float* __restrict__ b10,
               const float* __restrict__ b11, const float* __restrict__ b12,
               const float* __restrict__ wpo, const float* __restrict__ bpo,
               float* __restrict__ out) {
    const int tid = threadIdx.x;
    const int pg0 = blockIdx.x * NP;
    const int b   = pg0 >> 15;

    extern __shared__ char sm[];
    float* yf = reinterpret_cast<float*>(sm + SM_YF);

    __shared__ float s_inv[12];
    __shared__ float s_qw[NP][3];
    __shared__ float s_sub[NP][3];
    __shared__ float s_mf[NP];
    __shared__ int   s_bot[NP][3];
    __shared__ int   s_voff[NU];
    __shared__ float s_cw[NU][3];
    __shared__ float s_wtri[NU];

    // --- affine inverse (last row assumed [0,0,0,1]) ---
    if (tid == 0) {
        const float* A = affine_g + b * 16;
        float a00 = A[0], a01 = A[1], a02 = A[2],  t0 = A[3];
        float a10 = A[4], a11 = A[5], a12 = A[6],  t1 = A[7];
        float a20 = A[8], a21 = A[9], a22 = A[10], t2 = A[11];
        float c00 = a11 * a22 - a12 * a21;
        float c01 = a02 * a21 - a01 * a22;
        float c02 = a01 * a12 - a02 * a11;
        float det = a00 * c00 + a10 * c01 + a20 * c02;
        float id  = 1.0f / det;
        float i00 = c00 * id, i01 = c01 * id, i02 = c02 * id;
        float i10 = (a12 * a20 - a10 * a22) * id;
        float i11 = (a00 * a22 - a02 * a20) * id;
        float i12 = (a02 * a10 - a00 * a12) * id;
        float i20 = (a10 * a21 - a11 * a20) * id;
        float i21 = (a01 * a20 - a00 * a21) * id;
        float i22 = (a00 * a11 - a01 * a10) * id;
        s_inv[0] = i00; s_inv[1] = i01; s_inv[2]  = i02; s_inv[3]  = -(i00 * t0 + i01 * t1 + i02 * t2);
        s_inv[4] = i10; s_inv[5] = i11; s_inv[6]  = i12; s_inv[7]  = -(i10 * t0 + i11 * t1 + i12 * t2);
        s_inv[8] = i20; s_inv[9] = i21; s_inv[10] = i22; s_inv[11] = -(i20 * t0 + i21 * t1 + i22 * t2);
    }
    __syncthreads();

    // --- per-point setup ---
    if (tid < NP) {
        int pg = pg0 + tid;
        float mf = (mask_g[pg] != 0) ? 1.0f : 0.0f;
        const float* qp = qw_g + (mf != 0.0f ? (long)pg * 3
                                             : ((long)b * NPTS + NPTS / 2) * 3);
        float q0 = qp[0], q1 = qp[1], q2 = qp[2];
        s_qw[tid][0] = q0; s_qw[tid][1] = q1; s_qw[tid][2] = q2;
        s_mf[tid] = mf;
#pragma unroll
        for (int r = 0; r < 3; ++r) {
            float qv = s_inv[r * 4 + 0] * q0 + s_inv[r * 4 + 1] * q1 +
                       s_inv[r * 4 + 2] * q2 + s_inv[r * 4 + 3];
            float fb = floorf(qv);
            s_bot[tid][r] = (int)fb;
            s_sub[tid][r] = qv - fb;
        }
    }
    __syncthreads();

    // --- per-unit voxel, cw, trilinear weight ---
    if (tid < NU) {
        int pt = tid >> 3, c = tid & 7;
        int o0 = (c >> 2) & 1, o1 = (c >> 1) & 1, o2 = c & 1;
        int i0 = min(max(s_bot[pt][0] + o0, 0), G - 1);
        int i1 = min(max(s_bot[pt][1] + o1, 0), G - 1);
        int i2 = min(max(s_bot[pt][2] + o2, 0), G - 1);
        int sp = (i0 * G + i1) * G + i2;
        s_voff[tid] = (b * NPTS + sp) * CCH;
        const float* gp = grid_g + (long)(b * NPTS + sp) * 3;
        s_cw[tid][0] = gp[0]; s_cw[tid][1] = gp[1]; s_cw[tid][2] = gp[2];
        float ww0 = o0 ? s_sub[pt][0] : 1.0f - s_sub[pt][0];
        float ww1 = o1 ? s_sub[pt][1] : 1.0f - s_sub[pt][1];
        float ww2 = o2 ? s_sub[pt][2] : 1.0f - s_sub[pt][2];
        s_wtri[tid] = ww0 * ww1 * ww2;
    }
    __syncthreads();

    // --- feature gather: yf + H rows 0..95 (channel pairs) ---
    u32* Hp = reinterpret_cast<u32*>(sm + SM_H);
#pragma unroll
    for (int rep = 0; rep < 24; ++rep) {
        int idx = tid + rep * THREADS;       // < 3072 = 64u * 48 ch-pairs
        int u = idx / 48, cp = idx % 48;
        float mf = s_mf[u >> 3];
        const float* src = g_cvt + s_voff[u] + 2 * cp;
        float vx = src[0] * mf, vy = src[1] * mf;
        yf[(2 * cp) * YSTR + u]     = vx;
        yf[(2 * cp + 1) * YSTR + u] = vy;
        Hp[u * S_H + cp] = (u32)hbits(vx) | ((u32)hbits(vy) << 16);
    }
    // --- H rows 96..101: cw, qw (384 entries) ---
#pragma unroll
    for (int it = 0; it < 3; ++it) {
        int idx = tid + it * THREADS;
        int u = idx / 6, r = idx % 6;
        float mf = s_mf[u >> 3];
        float v = (r < 3) ? s_cw[u][r] : s_qw[u >> 3][r - 3];
        write_h(sm, u, 96 + r, v * mf);
    }
    // --- H rows 102..173: fourier (2304 entries) ---
#pragma unroll
    for (int it = 0; it < 18; ++it) {
        int idx = tid + it * THREADS;
        int u = idx / 36, e = idx % 36;
        int a = e / 12, j = e % 12;
        int pt = u >> 3, c = u & 7;
        int off = (a == 0) ? ((c >> 2) & 1) : ((a == 1) ? ((c >> 1) & 1) : (c & 1));
        float rel = (s_sub[pt][a] - (float)off + 1.0f) * 0.5f;
        float f = exp2f((float)j * 0.13208020839342967f);   // 3^(j/12)
        float ang = 6.283185307179586f * f * rel;
        float sv, cv;
        __sincosf(ang, &sv, &cv);
        float mf = s_mf[pt];
        write_h(sm, u, 102 + a * 24 + j,      sv * mf);
        write_h(sm, u, 102 + a * 24 + 12 + j, cv * mf);
    }
    // --- H rows 174..175: zero pad (word 87 per unit) ---
    if (tid < NU) {
        Hp[tid * S_H + 87] = 0;
    }
    __syncthreads();

    // --- 6 MLP layers on tensor cores ---
    const int lane = tid & 31;
    const int w    = tid >> 5;
    const int wm   = w & 1;       // m-half (48 channels)
    const int wn   = w >> 1;      // n-half (32 units)

    run_layer<11, 0,  false, true >(sm, b00, lane, wm, wn);
    run_layer<6,  11, false, true >(sm, b01, lane, wm, wn);
    run_layer<6,  17, true,  true >(sm, b02, lane, wm, wn);
    run_layer<11, 23, false, true >(sm, b10, lane, wm, wn);
    run_layer<6,  34, false, true >(sm, b11, lane, wm, wn);
    run_layer<6,  40, true,  false>(sm, b12, lane, wm, wn);

    // --- trilinear reduce: ybar = sum_c wtri_c * y_c (sum wtri == 1) ---
    // s_red overlays the (now dead) H region.
    float* s_red = reinterpret_cast<float*>(sm);
#pragma unroll
    for (int it = 0; it < 6; ++it) {
        int idx = tid + it * THREADS;        // < 768 = 96ch x 8pt
        int ch = idx >> 3, pt = idx & 7;
        float acc = 0.0f;
#pragma unroll
        for (int c = 0; c < 8; ++c)
            acc += s_wtri[pt * 8 + c] * yf[ch * YSTR + pt * 8 + c];
        s_red[ch * NP + pt] = acc;
    }
    __syncthreads();

    // --- post layer: 96 -> 45, 8 points ---
    if (tid < OUTC) {
        float a[NP];
        float bv = __ldg(bpo + tid);
#pragma unroll
        for (int p = 0; p < NP; ++p) a[p] = bv;
#pragma unroll 4
        for (int k = 0; k < CCH; ++k) {
            float wv = __ldg(wpo + k * OUTC + tid);
#pragma unroll
            for (int p = 0; p < NP; ++p)
                a[p] = fmaf(s_red[k * NP + p], wv, a[p]);
        }
        int n0 = pg0 & (NPTS - 1);
        long base = ((long)b * OUTC + tid) * NPTS + n0;
#pragma unroll
        for (int p = 0; p < NP; ++p)
            out[base + p] = a[p];
    }
}

// ---------------------------------------------------------------------------
extern "C" void kernel_launch(void* const* d_in, const int* in_sizes, int n_in,
                              void* d_out, int out_size) {
    const float* context_v = (const float*)d_in[0];
    const float* grid      = (const float*)d_in[1];
    const float* qw        = (const float*)d_in[2];
    const int*   mask      = (const int*)d_in[3];
    const float* affine    = (const float*)d_in[4];
    const float* w00 = (const float*)d_in[8],  *b00 = (const float*)d_in[9];
    const float* w01 = (const float*)d_in[10], *b01 = (const float*)d_in[11];
    const float* w02 = (const float*)d_in[12], *b02 = (const float*)d_in[13];
    const float* w10 = (const float*)d_in[14], *b10 = (const float*)d_in[15];
    const float* w11 = (const float*)d_in[16], *b11 = (const float*)d_in[17];
    const float* w12 = (const float*)d_in[18], *b12 = (const float*)d_in[19];
    const float* wpo = (const float*)d_in[20], *bpo = (const float*)d_in[21];
    float* out = (float*)d_out;

    static int configured = 0;
    if (!configured) {
        cudaFuncSetAttribute(decoder_kernel,
                             cudaFuncAttributeMaxDynamicSharedMemorySize,
                             SM_TOT);
        configured = 1;
    }

    int frag_blocks = (NSG * 12 * 32 + 255) / 256;   // 69
    prep_kernel<<<1024 + frag_blocks, 256>>>(context_v, w00, w01, w02, w10, w11, w12);
    decoder_kernel<<<(NBATCH * NPTS) / NP, THREADS, SM_TOT>>>(
        qw, mask, grid, affine,
        b00, b01, b02, b10, b11, b12,
        wpo, bpo, out);
}

// round 16
// speedup vs baseline: 1.1601x; 1.1601x over previous
#include <cuda_runtime.h>
#include <cuda_fp16.h>
#include <cstdint>

// ----------------------------------------------------------------------------
// Decoder_61237643706389 — mma.sync HMMA fp16 2-product path, round 16.
// 192-thread blocks (6 warps = 3m x 2n), warp tile 32ch x 32u:
// 4 A-LDG.128 + 8 B-LDS per warp-kstep feeding 16 mma (1.5 wf/mma, r14 was
// 2.33) with only 32 accumulator regs -> 4 blocks x 6 warps = 24 warps/SM.
// Combines r15's A-traffic halving with near-r14 occupancy.
// ----------------------------------------------------------------------------

typedef unsigned int       u32;
typedef unsigned long long u64;

#define G        32
#define NBATCH   2
#define CCH      96
#define NPTS     32768
#define OUTC     45
#define NP       8
#define NU       64
#define THREADS  192

#define S_H      92             // H row stride in 32-bit words (92 mod 32 = 28)
#define YSTR     65             // yf row stride in floats

// dynamic smem layout (bytes)
#define SM_H     0                          // H fp16: 64 rows x 92 words = 23552
#define SM_YF    23552                      // yf fp32 [96][YSTR] = 24960
#define SM_TOT   (23552 + CCH * YSTR * 4)   // 48512

// Transposed context features: [B][x][y][z][C], contiguous C.
__device__ float g_cvt[NBATCH * NPTS * CCH];
// Pre-packed A fragments (fp16): idx = ((sg*6 + mtg)*2 + split)*32 + lane.
#define NSG 46
__device__ uint4 g_wf[NSG * 12 * 32];

__device__ __forceinline__ float silu_f(float x) {
    return x / (1.0f + __expf(-x));
}
__device__ __forceinline__ unsigned short hbits(float v) {
    __half h = __float2half(v);
    return *reinterpret_cast<unsigned short*>(&h);
}
__device__ __forceinline__ float hval(float v) {
    return __half2float(__float2half(v));
}

__device__ __forceinline__ void mma16816(float (&d)[4], uint4 a, u32 b0, u32 b1) {
    asm volatile(
        "mma.sync.aligned.m16n8k16.row.col.f32.f16.f16.f32 "
        "{%0,%1,%2,%3}, {%4,%5,%6,%7}, {%8,%9}, {%0,%1,%2,%3};"
        : "+f"(d[0]), "+f"(d[1]), "+f"(d[2]), "+f"(d[3])
        : "r"(a.x), "r"(a.y), "r"(a.z), "r"(a.w), "r"(b0), "r"(b1));
}

// write one activation value (fp16) into H. u = unit, k = row.
__device__ __forceinline__ void write_h(char* sm, int u, int k, float v) {
    int off = (u * S_H + (k >> 1)) * 4 + (k & 1) * 2;
    *reinterpret_cast<unsigned short*>(sm + SM_H + off) = hbits(v);
}

// ---------------------------------------------------------------------------
// Merged prep: blocks [0,1024) transpose context_v; blocks [1024,..) pack
// weights into mma A-fragment layout (fp16 hi/lo split).
// ---------------------------------------------------------------------------
__global__ void prep_kernel(const float* __restrict__ ctx,
                            const float* __restrict__ w00, const float* __restrict__ w01,
                            const float* __restrict__ w02, const float* __restrict__ w10,
                            const float* __restrict__ w11, const float* __restrict__ w12) {
    __shared__ float tile[CCH][65];
    if (blockIdx.x < 1024) {
        int bs = blockIdx.x;
        int b  = bs >> 9;
        int s0 = (bs & 511) * 64;
        for (int idx = threadIdx.x; idx < CCH * 64; idx += blockDim.x) {
            int c = idx >> 6, so = idx & 63;
            tile[c][so] = ctx[((long)(b * CCH + c) << 15) + s0 + so];
        }
        __syncthreads();
        for (int idx = threadIdx.x; idx < CCH * 64; idx += blockDim.x) {
            int so = idx / CCH, c = idx % CCH;
            g_cvt[(((long)b << 15) + s0 + so) * CCH + c] = tile[c][so];
        }
        return;
    }
    int idx = (blockIdx.x - 1024) * blockDim.x + threadIdx.x;
    if (idx >= NSG * 12 * 32) return;
    int lane = idx & 31;
    int t = idx >> 5;
    int split = t & 1; t >>= 1;
    int mtg = t % 6;
    int sg = t / 6;
    const float* W; int K; int sb;
    if      (sg < 11) { W = w00; K = 174; sb = 0;  }
    else if (sg < 17) { W = w01; K = 96;  sb = 11; }
    else if (sg < 23) { W = w02; K = 96;  sb = 17; }
    else if (sg < 34) { W = w10; K = 174; sb = 23; }
    else if (sg < 40) { W = w11; K = 96;  sb = 34; }
    else              { W = w12; K = 96;  sb = 40; }
    int k0 = (sg - sb) * 16 + 2 * (lane & 3);
    int m0 = mtg * 16 + (lane >> 2);

    auto get = [&](int k, int m) -> u32 {
        float v = (k < K) ? __ldg(W + k * 96 + m) : 0.0f;
        float h = hval(v);
        return (u32)hbits(split ? (v - h) : v);
    };
    uint4 r;
    r.x = get(k0, m0)     | (get(k0 + 1, m0)     << 16);
    r.y = get(k0, m0 + 8) | (get(k0 + 1, m0 + 8) << 16);
    r.z = get(k0 + 8, m0)     | (get(k0 + 9, m0)     << 16);
    r.w = get(k0 + 8, m0 + 8) | (get(k0 + 9, m0 + 8) << 16);
    g_wf[idx] = r;
}

// ---------------------------------------------------------------------------
// One MLP layer on tensor cores. Warp (wm, wn): 32ch x 32u -> 2mt x 4nt tiles,
// 2 products (Whi*H + Wlo*H) per tile per k-step.
// ---------------------------------------------------------------------------
template <int K16, int BASE, bool RES, bool WRITEH>
__device__ __forceinline__ void run_layer(char* sm, const float* __restrict__ bias,
                                          int lane, int wm, int wn) {
    float* yf = reinterpret_cast<float*>(sm + SM_YF);
    const u32* Hp = reinterpret_cast<const u32*>(sm + SM_H);

    float d[2][4][4];
#pragma unroll
    for (int mt = 0; mt < 2; ++mt) {
        int r0 = wm * 32 + mt * 16 + (lane >> 2);
        float blo = __ldg(bias + r0), bhi = __ldg(bias + r0 + 8);
#pragma unroll
        for (int nt = 0; nt < 4; ++nt) {
            d[mt][nt][0] = blo; d[mt][nt][1] = blo;
            d[mt][nt][2] = bhi; d[mt][nt][3] = bhi;
        }
    }

    const uint4* ap = g_wf + (size_t)((BASE * 6 + wm * 2) * 2) * 32 + lane;
    const int wbase = (wn * 32 + (lane >> 2)) * S_H + (lane & 3);

#pragma unroll 2
    for (int s = 0; s < K16; ++s) {
        u32 bh[4][2];
#pragma unroll
        for (int nt = 0; nt < 4; ++nt) {
            int w = wbase + nt * 8 * S_H + s * 8;
            bh[nt][0] = Hp[w]; bh[nt][1] = Hp[w + 4];
        }
        const uint4* aps = ap + (size_t)s * 384;
#pragma unroll
        for (int mt = 0; mt < 2; ++mt) {
            uint4 ah = __ldg(aps + mt * 64);
            uint4 al = __ldg(aps + mt * 64 + 32);
#pragma unroll
            for (int nt = 0; nt < 4; ++nt) {
                mma16816(d[mt][nt], ah, bh[nt][0], bh[nt][1]);
                mma16816(d[mt][nt], al, bh[nt][0], bh[nt][1]);
            }
        }
    }
    __syncthreads();   // all warps done reading H before overwriting

#pragma unroll
    for (int mt = 0; mt < 2; ++mt) {
        int r0 = wm * 32 + mt * 16 + (lane >> 2);
#pragma unroll
        for (int nt = 0; nt < 4; ++nt) {
            int c0 = wn * 32 + nt * 8 + 2 * (lane & 3);
            int rr[4] = { r0, r0, r0 + 8, r0 + 8 };
            int cc[4] = { c0, c0 + 1, c0, c0 + 1 };
#pragma unroll
            for (int e = 0; e < 4; ++e) {
                float h = silu_f(d[mt][nt][e]);
                if (RES) {
                    h += yf[rr[e] * YSTR + cc[e]];
                    yf[rr[e] * YSTR + cc[e]] = h;
                }
                if (WRITEH) write_h(sm, cc[e], rr[e], h);
            }
        }
    }
    __syncthreads();
}

// ---------------------------------------------------------------------------
// Main kernel: 8 points x 8 corners = 64 units, 192 threads (6 warps).
// ---------------------------------------------------------------------------
__global__ void __launch_bounds__(THREADS, 4)
decoder_kernel(const float* __restrict__ qw_g,
               const int* __restrict__ mask_g,
               const float* __restrict__ grid_g,
               const float* __restrict__ affine_g,
               const float* __restrict__ b00, const float* __restrict__ b01,
               const float* __restrict__ b02, const float* __restrict__ b10,
               const float* __restrict__ b11, const float* __restrict__ b12,
               const float* __restrict__ wpo, const float* __restrict__ bpo,
               float* __restrict__ out) {
    const int tid = threadIdx.x;
    const int pg0 = blockIdx.x * NP;
    const int b   = pg0 >> 15;

    extern __shared__ char sm[];
    float* yf = reinterpret_cast<float*>(sm + SM_YF);

    __shared__ float s_inv[12];
    __shared__ float s_qw[NP][3];
    __shared__ float s_sub[NP][3];
    __shared__ float s_mf[NP];
    __shared__ int   s_bot[NP][3];
    __shared__ int   s_voff[NU];
    __shared__ float s_cw[NU][3];
    __shared__ float s_wtri[NU];

    // --- affine inverse (last row assumed [0,0,0,1]) ---
    if (tid == 0) {
        const float* A = affine_g + b * 16;
        float a00 = A[0], a01 = A[1], a02 = A[2],  t0 = A[3];
        float a10 = A[4], a11 = A[5], a12 = A[6],  t1 = A[7];
        float a20 = A[8], a21 = A[9], a22 = A[10], t2 = A[11];
        float c00 = a11 * a22 - a12 * a21;
        float c01 = a02 * a21 - a01 * a22;
        float c02 = a01 * a12 - a02 * a11;
        float det = a00 * c00 + a10 * c01 + a20 * c02;
        float id  = 1.0f / det;
        float i00 = c00 * id, i01 = c01 * id, i02 = c02 * id;
        float i10 = (a12 * a20 - a10 * a22) * id;
        float i11 = (a00 * a22 - a02 * a20) * id;
        float i12 = (a02 * a10 - a00 * a12) * id;
        float i20 = (a10 * a21 - a11 * a20) * id;
        float i21 = (a01 * a20 - a00 * a21) * id;
        float i22 = (a00 * a11 - a01 * a10) * id;
        s_inv[0] = i00; s_inv[1] = i01; s_inv[2]  = i02; s_inv[3]  = -(i00 * t0 + i01 * t1 + i02 * t2);
        s_inv[4] = i10; s_inv[5] = i11; s_inv[6]  = i12; s_inv[7]  = -(i10 * t0 + i11 * t1 + i12 * t2);
        s_inv[8] = i20; s_inv[9] = i21; s_inv[10] = i22; s_inv[11] = -(i20 * t0 + i21 * t1 + i22 * t2);
    }
    __syncthreads();

    // --- per-point setup ---
    if (tid < NP) {
        int pg = pg0 + tid;
        float mf = (mask_g[pg] != 0) ? 1.0f : 0.0f;
        const float* qp = qw_g + (mf != 0.0f ? (long)pg * 3
                                             : ((long)b * NPTS + NPTS / 2) * 3);
        float q0 = qp[0], q1 = qp[1], q2 = qp[2];
        s_qw[tid][0] = q0; s_qw[tid][1] = q1; s_qw[tid][2] = q2;
        s_mf[tid] = mf;
#pragma unroll
        for (int r = 0; r < 3; ++r) {
            float qv = s_inv[r * 4 + 0] * q0 + s_inv[r * 4 + 1] * q1 +
                       s_inv[r * 4 + 2] * q2 + s_inv[r * 4 + 3];
            float fb = floorf(qv);
            s_bot[tid][r] = (int)fb;
            s_sub[tid][r] = qv - fb;
        }
    }
    __syncthreads();

    // --- per-unit voxel, cw, trilinear weight ---
    if (tid < NU) {
        int pt = tid >> 3, c = tid & 7;
        int o0 = (c >> 2) & 1, o1 = (c >> 1) & 1, o2 = c & 1;
        int i0 = min(max(s_bot[pt][0] + o0, 0), G - 1);
        int i1 = min(max(s_bot[pt][1] + o1, 0), G - 1);
        int i2 = min(max(s_bot[pt][2] + o2, 0), G - 1);
        int sp = (i0 * G + i1) * G + i2;
        s_voff[tid] = (b * NPTS + sp) * CCH;
        const float* gp = grid_g + (long)(b * NPTS + sp) * 3;
        s_cw[tid][0] = gp[0]; s_cw[tid][1] = gp[1]; s_cw[tid][2] = gp[2];
        float ww0 = o0 ? s_sub[pt][0] : 1.0f - s_sub[pt][0];
        float ww1 = o1 ? s_sub[pt][1] : 1.0f - s_sub[pt][1];
        float ww2 = o2 ? s_sub[pt][2] : 1.0f - s_sub[pt][2];
        s_wtri[tid] = ww0 * ww1 * ww2;
    }
    __syncthreads();

    // --- feature gather: yf + H rows 0..95 (channel pairs) ---
    u32* Hp = reinterpret_cast<u32*>(sm + SM_H);
#pragma unroll
    for (int rep = 0; rep < 16; ++rep) {
        int idx = tid + rep * THREADS;       // < 3072 = 64u * 48 ch-pairs
        int u = idx / 48, cp = idx % 48;
        float mf = s_mf[u >> 3];
        const float* src = g_cvt + s_voff[u] + 2 * cp;
        float vx = src[0] * mf, vy = src[1] * mf;
        yf[(2 * cp) * YSTR + u]     = vx;
        yf[(2 * cp + 1) * YSTR + u] = vy;
        Hp[u * S_H + cp] = (u32)hbits(vx) | ((u32)hbits(vy) << 16);
    }
    // --- H rows 96..101: cw, qw (384 entries) ---
#pragma unroll
    for (int it = 0; it < 2; ++it) {
        int idx = tid + it * THREADS;
        int u = idx / 6, r = idx % 6;
        float mf = s_mf[u >> 3];
        float v = (r < 3) ? s_cw[u][r] : s_qw[u >> 3][r - 3];
        write_h(sm, u, 96 + r, v * mf);
    }
    // --- H rows 102..173: fourier (2304 entries) ---
#pragma unroll
    for (int it = 0; it < 12; ++it) {
        int idx = tid + it * THREADS;
        int u = idx / 36, e = idx % 36;
        int a = e / 12, j = e % 12;
        int pt = u >> 3, c = u & 7;
        int off = (a == 0) ? ((c >> 2) & 1) : ((a == 1) ? ((c >> 1) & 1) : (c & 1));
        float rel = (s_sub[pt][a] - (float)off + 1.0f) * 0.5f;
        float f = exp2f((float)j * 0.13208020839342967f);   // 3^(j/12)
        float ang = 6.283185307179586f * f * rel;
        float sv, cv;
        __sincosf(ang, &sv, &cv);
        float mf = s_mf[pt];
        write_h(sm, u, 102 + a * 24 + j,      sv * mf);
        write_h(sm, u, 102 + a * 24 + 12 + j, cv * mf);
    }
    // --- H rows 174..175: zero pad (word 87 per unit) ---
    if (tid < NU) {
        Hp[tid * S_H + 87] = 0;
    }
    __syncthreads();

    // --- 6 MLP layers on tensor cores ---
    const int lane = tid & 31;
    const int w    = tid >> 5;
    const int wm   = w >> 1;      // m-third (32 channels)
    const int wn   = w & 1;       // n-half (32 units)

    run_layer<11, 0,  false, true >(sm, b00, lane, wm, wn);
    run_layer<6,  11, false, true >(sm, b01, lane, wm, wn);
    run_layer<6,  17, true,  true >(sm, b02, lane, wm, wn);
    run_layer<11, 23, false, true >(sm, b10, lane, wm, wn);
    run_layer<6,  34, false, true >(sm, b11, lane, wm, wn);
    run_layer<6,  40, true,  false>(sm, b12, lane, wm, wn);

    // --- trilinear reduce: ybar = sum_c wtri_c * y_c (sum wtri == 1) ---
    // s_red overlays the (now dead) H region.
    float* s_red = reinterpret_cast<float*>(sm);
#pragma unroll
    for (int it = 0; it < 4; ++it) {
        int idx = tid + it * THREADS;        // < 768 = 96ch x 8pt
        int ch = idx >> 3, pt = idx & 7;
        float acc = 0.0f;
#pragma unroll
        for (int c = 0; c < 8; ++c)
            acc += s_wtri[pt * 8 + c] * yf[ch * YSTR + pt * 8 + c];
        s_red[ch * NP + pt] = acc;
    }
    __syncthreads();

    // --- post layer: 96 -> 45, 8 points ---
    if (tid < OUTC) {
        float a[NP];
        float bv = __ldg(bpo + tid);
#pragma unroll
        for (int p = 0; p < NP; ++p) a[p] = bv;
#pragma unroll 4
        for (int k = 0; k < CCH; ++k) {
            float wv = __ldg(wpo + k * OUTC + tid);
#pragma unroll
            for (int p = 0; p < NP; ++p)
                a[p] = fmaf(s_red[k * NP + p], wv, a[p]);
        }
        int n0 = pg0 & (NPTS - 1);
        long base = ((long)b * OUTC + tid) * NPTS + n0;
#pragma unroll
        for (int p = 0; p < NP; ++p)
            out[base + p] = a[p];
    }
}

// ---------------------------------------------------------------------------
extern "C" void kernel_launch(void* const* d_in, const int* in_sizes, int n_in,
                              void* d_out, int out_size) {
    const float* context_v = (const float*)d_in[0];
    const float* grid      = (const float*)d_in[1];
    const float* qw        = (const float*)d_in[2];
    const int*   mask      = (const int*)d_in[3];
    const float* affine    = (const float*)d_in[4];
    const float* w00 = (const float*)d_in[8],  *b00 = (const float*)d_in[9];
    const float* w01 = (const float*)d_in[10], *b01 = (const float*)d_in[11];
    const float* w02 = (const float*)d_in[12], *b02 = (const float*)d_in[13];
    const float* w10 = (const float*)d_in[14], *b10 = (const float*)d_in[15];
    const float* w11 = (const float*)d_in[16], *b11 = (const float*)d_in[17];
    const float* w12 = (const float*)d_in[18], *b12 = (const float*)d_in[19];
    const float* wpo = (const float*)d_in[20], *bpo = (const float*)d_in[21];
    float* out = (float*)d_out;

    static int configured = 0;
    if (!configured) {
        cudaFuncSetAttribute(decoder_kernel,
                             cudaFuncAttributeMaxDynamicSharedMemorySize,
                             SM_TOT);
        configured = 1;
    }

    int frag_blocks = (NSG * 12 * 32 + 255) / 256;   // 69
    prep_kernel<<<1024 + frag_blocks, 256>>>(context_v, w00, w01, w02, w10, w11, w12);
    decoder_kernel<<<(NBATCH * NPTS) / NP, THREADS, SM_TOT>>>(
        qw, mask, grid, affine,
        b00, b01, b02, b10, b11, b12,
        wpo, bpo, out);
}